// round 5
// baseline (speedup 1.0000x reference)
#include <cuda_runtime.h>
#include <math.h>

#define MTOT   65536    // B*S
#define CQKV   128
#define FDIM   512
#define HC     128
#define NH     4
#define CH     32
#define SEQ    256
#define BATCH  256
#define INFV   1e9f

typedef unsigned long long u64;

// ---- packed fp32x2 helpers (Blackwell f32x2 pipe; bit-identical to 2x fmaf) ----
__device__ __forceinline__ void ffma2(u64& d, u64 a, u64 b) {
    asm("fma.rn.f32x2 %0, %1, %2, %0;" : "+l"(d) : "l"(a), "l"(b));
}
__device__ __forceinline__ void fmul2(u64& d, u64 a, u64 b) {
    asm("mul.rn.f32x2 %0, %1, %2;" : "=l"(d) : "l"(a), "l"(b));
}
__device__ __forceinline__ u64 bcast2(float x) {
    u64 d; asm("mov.b64 %0, {%1, %1};" : "=l"(d) : "f"(x)); return d;
}
__device__ __forceinline__ float2 unpk(u64 d) {
    float2 f; asm("mov.b64 {%0, %1}, %2;" : "=f"(f.x), "=f"(f.y) : "l"(d)); return f;
}

// Scratch (allocation-free): qkvg projection and gated attention output
__device__ float g_qkvg[(size_t)MTOT * FDIM];  // 128 MB
__device__ float g_og[(size_t)MTOT * HC];      //  32 MB

// ---------------------------------------------------------------------------
// Kernel 1: QKVG projection.  out[m][f] = dot(X[m][0:128], W[f][0:128])
// 64x64 tile, K in two 64-chunks, 4x4 register outputs, K-paired f32x2 FMA.
// ---------------------------------------------------------------------------
__global__ __launch_bounds__(256) void k_qkvg(const float* __restrict__ X,
                                              const float* __restrict__ W) {
    __shared__ __align__(16) float Xs[64][68];   // 68*4=272B row stride
    __shared__ __align__(16) float Ws[64][68];
    const int tid = threadIdx.x;
    const int tx = tid & 15, ty = tid >> 4;
    const int m0 = blockIdx.x * 64;
    const int f0 = blockIdx.y * 64;

    u64 acc2[4][4] = {};   // each holds a K-paired partial sum {even,odd}

    #pragma unroll
    for (int kt = 0; kt < 2; kt++) {
        #pragma unroll
        for (int i = 0; i < 4; i++) {
            int idx = tid + i * 256;            // float4 index
            int row = idx >> 4, c4 = idx & 15;  // 16 float4 per row
            *(float4*)&Xs[row][c4 * 4] =
                *(const float4*)&X[(size_t)(m0 + row) * 128 + kt * 64 + c4 * 4];
            *(float4*)&Ws[row][c4 * 4] =
                *(const float4*)&W[(size_t)(f0 + row) * 128 + kt * 64 + c4 * 4];
        }
        __syncthreads();
        #pragma unroll
        for (int k4 = 0; k4 < 16; k4++) {
            ulonglong2 a2[4], b2[4];
            #pragma unroll
            for (int i = 0; i < 4; i++) a2[i] = *(const ulonglong2*)&Xs[ty * 4 + i][k4 * 4];
            #pragma unroll
            for (int j = 0; j < 4; j++) b2[j] = *(const ulonglong2*)&Ws[tx * 4 + j][k4 * 4];
            #pragma unroll
            for (int i = 0; i < 4; i++)
                #pragma unroll
                for (int j = 0; j < 4; j++) {
                    ffma2(acc2[i][j], a2[i].x, b2[j].x);
                    ffma2(acc2[i][j], a2[i].y, b2[j].y);
                }
        }
        __syncthreads();
    }

    #pragma unroll
    for (int i = 0; i < 4; i++) {
        float4 v;
        #pragma unroll
        for (int j = 0; j < 4; j++) {
            float2 f = unpk(acc2[i][j]);
            ((float*)&v)[j] = f.x + f.y;
        }
        *(float4*)&g_qkvg[(size_t)(m0 + ty * 4 + i) * FDIM + f0 + tx * 4] = v;
    }
}

// ---------------------------------------------------------------------------
// Kernel 2: attention per (b, h) block. 256 threads; thread t owns query row t.
// K/V streamed through smem in two 128-row halves (33 KB static smem, no
// cudaFuncSetAttribute needed). Online softmax carries state across halves.
// QK / AV loops use K-paired f32x2 FMA. Fused mask, bias, sigmoid gating.
// ---------------------------------------------------------------------------
__global__ __launch_bounds__(256) void k_attn(const float* __restrict__ mask,
                                              const float* __restrict__ bias,
                                              const float* __restrict__ gbias) {
    __shared__ __align__(16) float Ks[128 * 32];   // 16 KB
    __shared__ __align__(16) float Vs[128 * 32];   // 16 KB
    __shared__ float maskS[256];                   // 1 KB

    const int tid = threadIdx.x;
    const int b = blockIdx.x;
    const int h = blockIdx.y;

    if (tid < 64) {
        *(float4*)&maskS[tid * 4] = *(const float4*)&mask[b * 256 + tid * 4];
    }

    // q row as 16 packed pairs (pre-scaled)
    const u64 scale2 = bcast2(0.17677669529663688f);  // 1/sqrt(32)
    u64 qd[16];
    {
        const u64* qp = (const u64*)(g_qkvg + (size_t)(b * 256 + tid) * FDIM + h * CH);
        #pragma unroll
        for (int c2 = 0; c2 < 16; c2++) {
            u64 v = qp[c2];
            fmul2(qd[c2], v, scale2);
        }
    }

    const float* biasRow = bias + (size_t)h * 65536 + (size_t)tid * 256;

    u64 accD[16] = {};
    float mcur = -1e30f, l = 0.f;

    #pragma unroll 1
    for (int half = 0; half < 2; half++) {
        __syncthreads();   // previous half fully consumed before overwrite
        // load K,V rows [half*128, half*128+128): 1024 float4 each, 4/thread
        #pragma unroll
        for (int i = 0; i < 4; i++) {
            int idx = tid + i * 256;
            int row = idx >> 3, c4 = idx & 7;
            const float* base =
                g_qkvg + (size_t)(b * 256 + half * 128 + row) * FDIM + h * CH + c4 * 4;
            *(float4*)&Ks[row * 32 + c4 * 4] = *(const float4*)(base + 128);
            *(float4*)&Vs[row * 32 + c4 * 4] = *(const float4*)(base + 256);
        }
        __syncthreads();

        for (int j0 = 0; j0 < 128; j0 += 32) {
            const int jg = half * 128 + j0;   // global key offset
            float s[32];
            // init with bias + mask term
            #pragma unroll
            for (int j4 = 0; j4 < 8; j4++) {
                float4 bv = *(const float4*)&biasRow[jg + j4 * 4];
                s[j4 * 4 + 0] = bv.x + (maskS[jg + j4 * 4 + 0] - 1.f) * INFV;
                s[j4 * 4 + 1] = bv.y + (maskS[jg + j4 * 4 + 1] - 1.f) * INFV;
                s[j4 * 4 + 2] = bv.z + (maskS[jg + j4 * 4 + 2] - 1.f) * INFV;
                s[j4 * 4 + 3] = bv.w + (maskS[jg + j4 * 4 + 3] - 1.f) * INFV;
            }
            // scores: paired dot, 2 accumulators for latency cover
            #pragma unroll
            for (int j = 0; j < 32; j++) {
                const u64* kr = (const u64*)&Ks[(j0 + j) * 32];
                u64 d2a = 0, d2b = 0;
                #pragma unroll
                for (int c2 = 0; c2 < 16; c2 += 2) {
                    ffma2(d2a, qd[c2], kr[c2]);
                    ffma2(d2b, qd[c2 + 1], kr[c2 + 1]);
                }
                float2 fa = unpk(d2a), fb = unpk(d2b);
                s[j] += (fa.x + fa.y) + (fb.x + fb.y);
            }
            // tile max
            float tm = s[0];
            #pragma unroll
            for (int j = 1; j < 32; j++) tm = fmaxf(tm, s[j]);
            float mnew = fmaxf(mcur, tm);
            float alpha = __expf(mcur - mnew);
            l *= alpha;
            u64 al2 = bcast2(alpha);
            #pragma unroll
            for (int c2 = 0; c2 < 16; c2++) fmul2(accD[c2], accD[c2], al2);
            // exp + AV (paired)
            #pragma unroll
            for (int j = 0; j < 32; j++) {
                float p = __expf(s[j] - mnew);
                l += p;
                u64 p2 = bcast2(p);
                const u64* vr = (const u64*)&Vs[(j0 + j) * 32];
                #pragma unroll
                for (int c2 = 0; c2 < 16; c2++) ffma2(accD[c2], p2, vr[c2]);
            }
            mcur = mnew;
        }
    }

    // epilogue: normalize + sigmoid gate, write g_og
    const float inv = 1.f / l;
    const size_t m = (size_t)b * 256 + tid;
    const float* grow = g_qkvg + m * FDIM + 384 + h * CH;
    float* orow = g_og + m * HC + h * CH;
    #pragma unroll
    for (int c4 = 0; c4 < 8; c4++) {
        float4 gv = *(const float4*)(grow + c4 * 4);
        float4 gb = *(const float4*)(gbias + h * CH + c4 * 4);
        float2 a0 = unpk(accD[c4 * 2]);
        float2 a1 = unpk(accD[c4 * 2 + 1]);
        float4 o;
        o.x = a0.x * inv * (1.f / (1.f + __expf(-(gv.x + gb.x))));
        o.y = a0.y * inv * (1.f / (1.f + __expf(-(gv.y + gb.y))));
        o.z = a1.x * inv * (1.f / (1.f + __expf(-(gv.z + gb.z))));
        o.w = a1.y * inv * (1.f / (1.f + __expf(-(gv.w + gb.w))));
        *(float4*)(orow + c4 * 4) = o;
    }
}

// ---------------------------------------------------------------------------
// Kernel 3: output projection + bias + transposed add + transposed store.
// proj[m][oc] = dot(g_og[m], W_o[oc]) + b_o[oc]
// out[0,s,b,oc] = add[0,s,b,oc] + proj[0,b,s,oc]   (m = b*256 + s)
// ---------------------------------------------------------------------------
__global__ __launch_bounds__(256) void k_out(const float* __restrict__ Wo,
                                             const float* __restrict__ bo,
                                             const float* __restrict__ add,
                                             float* __restrict__ out) {
    __shared__ __align__(16) float As[64][68];
    __shared__ __align__(16) float Ws[64][68];
    const int tid = threadIdx.x;
    const int tx = tid & 15, ty = tid >> 4;
    const int m0 = blockIdx.x * 64;
    const int f0 = blockIdx.y * 64;

    u64 acc2[4][4] = {};

    #pragma unroll
    for (int kt = 0; kt < 2; kt++) {
        #pragma unroll
        for (int i = 0; i < 4; i++) {
            int idx = tid + i * 256;
            int row = idx >> 4, c4 = idx & 15;
            *(float4*)&As[row][c4 * 4] =
                *(const float4*)&g_og[(size_t)(m0 + row) * HC + kt * 64 + c4 * 4];
            *(float4*)&Ws[row][c4 * 4] =
                *(const float4*)&Wo[(size_t)(f0 + row) * HC + kt * 64 + c4 * 4];
        }
        __syncthreads();
        #pragma unroll
        for (int k4 = 0; k4 < 16; k4++) {
            ulonglong2 a2[4], b2[4];
            #pragma unroll
            for (int i = 0; i < 4; i++) a2[i] = *(const ulonglong2*)&As[ty * 4 + i][k4 * 4];
            #pragma unroll
            for (int j = 0; j < 4; j++) b2[j] = *(const ulonglong2*)&Ws[tx * 4 + j][k4 * 4];
            #pragma unroll
            for (int i = 0; i < 4; i++)
                #pragma unroll
                for (int j = 0; j < 4; j++) {
                    ffma2(acc2[i][j], a2[i].x, b2[j].x);
                    ffma2(acc2[i][j], a2[i].y, b2[j].y);
                }
        }
        __syncthreads();
    }

    const float4 bo4 = *(const float4*)&bo[f0 + tx * 4];
    #pragma unroll
    for (int i = 0; i < 4; i++) {
        int m = m0 + ty * 4 + i;
        int bb = m >> 8, ss = m & 255;
        size_t oidx = ((size_t)ss * 256 + bb) * 128 + f0 + tx * 4;
        float4 ad = *(const float4*)&add[oidx];
        float2 f0v = unpk(acc2[i][0]), f1v = unpk(acc2[i][1]);
        float2 f2v = unpk(acc2[i][2]), f3v = unpk(acc2[i][3]);
        float4 v;
        v.x = (f0v.x + f0v.y) + bo4.x + ad.x;
        v.y = (f1v.x + f1v.y) + bo4.y + ad.y;
        v.z = (f2v.x + f2v.y) + bo4.z + ad.z;
        v.w = (f3v.x + f3v.y) + bo4.w + ad.w;
        *(float4*)&out[oidx] = v;
    }
}

// ---------------------------------------------------------------------------
extern "C" void kernel_launch(void* const* d_in, const int* in_sizes, int n_in,
                              void* d_out, int out_size) {
    const float* x     = (const float*)d_in[0];  // input_qkv [1,256,256,128]
    const float* mask  = (const float*)d_in[1];  // [1,256,1,1,256]
    const float* bias  = (const float*)d_in[2];  // [1,1,4,256,256]
    const float* add   = (const float*)d_in[3];  // [1,256,256,128]
    const float* Wq    = (const float*)d_in[4];  // [512,128]
    const float* gb    = (const float*)d_in[5];  // [128]
    const float* Wo    = (const float*)d_in[6];  // [128,128]
    const float* bo    = (const float*)d_in[7];  // [128]
    float* out = (float*)d_out;

    k_qkvg<<<dim3(MTOT / 64, FDIM / 64), 256>>>(x, Wq);
    k_attn<<<dim3(BATCH, NH), 256>>>(mask, bias, gb);
    k_out<<<dim3(MTOT / 64, HC / 64), 256>>>(Wo, bo, add, out);
}

// round 10
// speedup vs baseline: 1.4664x; 1.4664x over previous
#include <cuda_runtime.h>
#include <math.h>

#define MTOT   65536    // B*S
#define CQKV   128
#define FDIM   512
#define HC     128
#define NH     4
#define CH     32
#define SEQ    256
#define BATCH  256
#define INFV   1e9f

typedef unsigned long long u64;

// ---- packed fp32x2 helpers (Blackwell f32x2 pipe; bit-identical to 2x fmaf) ----
__device__ __forceinline__ void ffma2(u64& d, u64 a, u64 b) {
    asm("fma.rn.f32x2 %0, %1, %2, %0;" : "+l"(d) : "l"(a), "l"(b));
}
__device__ __forceinline__ void fmul2(u64& d, u64 a, u64 b) {
    asm("mul.rn.f32x2 %0, %1, %2;" : "=l"(d) : "l"(a), "l"(b));
}
__device__ __forceinline__ u64 bcast2(float x) {
    u64 d; asm("mov.b64 %0, {%1, %1};" : "=l"(d) : "f"(x)); return d;
}
__device__ __forceinline__ float2 unpk(u64 d) {
    float2 f; asm("mov.b64 {%0, %1}, %2;" : "=f"(f.x), "=f"(f.y) : "l"(d)); return f;
}

// Scratch (allocation-free): qkvg projection and gated attention output
__device__ float g_qkvg[(size_t)MTOT * FDIM];  // 128 MB
__device__ float g_og[(size_t)MTOT * HC];      //  32 MB

// ---------------------------------------------------------------------------
// Kernel 1: QKVG projection.  out[m][f] = dot(X[m][0:128], W[f][0:128])
// 64x64 tile, K in two 64-chunks, 4x4 register outputs, K-paired f32x2 FMA.
// Smem tiles XOR-chunk-swizzled: chunk c4 of row r stored at c4^((r>>2)&15).
// Read pattern: a-chunk = k4^ty (broadcast pairs), b-chunk = k4^tx -> 16
// distinct chunks, each 16B bank position hit exactly twice = 2-way floor
// (was 8-way with the padded layout; round-5 ncu: L1=97%, fma=21%).
// ---------------------------------------------------------------------------
__global__ __launch_bounds__(256) void k_qkvg(const float* __restrict__ X,
                                              const float* __restrict__ W) {
    __shared__ __align__(16) float Xs[64][64];   // 16 KB, swizzled
    __shared__ __align__(16) float Ws[64][64];   // 16 KB, swizzled
    const int tid = threadIdx.x;
    const int tx = tid & 15, ty = tid >> 4;
    const int m0 = blockIdx.x * 64;
    const int f0 = blockIdx.y * 64;

    u64 acc2[4][4] = {};   // each holds a K-paired partial sum {even,odd}

    #pragma unroll
    for (int kt = 0; kt < 2; kt++) {
        #pragma unroll
        for (int i = 0; i < 4; i++) {
            int idx = tid + i * 256;            // float4 index
            int row = idx >> 4, c4 = idx & 15;  // 16 float4 chunks per row
            int sc4 = c4 ^ ((row >> 2) & 15);   // swizzled chunk position
            *(float4*)&Xs[row][sc4 * 4] =
                *(const float4*)&X[(size_t)(m0 + row) * 128 + kt * 64 + c4 * 4];
            *(float4*)&Ws[row][sc4 * 4] =
                *(const float4*)&W[(size_t)(f0 + row) * 128 + kt * 64 + c4 * 4];
        }
        __syncthreads();
        #pragma unroll
        for (int k4 = 0; k4 < 16; k4++) {
            const int pa = (k4 ^ ty) * 4;       // a rows are ty*4+i -> (r>>2)=ty
            const int pb = (k4 ^ tx) * 4;       // b rows are tx*4+j -> (r>>2)=tx
            ulonglong2 a2[4], b2[4];
            #pragma unroll
            for (int i = 0; i < 4; i++) a2[i] = *(const ulonglong2*)&Xs[ty * 4 + i][pa];
            #pragma unroll
            for (int j = 0; j < 4; j++) b2[j] = *(const ulonglong2*)&Ws[tx * 4 + j][pb];
            #pragma unroll
            for (int i = 0; i < 4; i++)
                #pragma unroll
                for (int j = 0; j < 4; j++) {
                    ffma2(acc2[i][j], a2[i].x, b2[j].x);
                    ffma2(acc2[i][j], a2[i].y, b2[j].y);
                }
        }
        __syncthreads();
    }

    #pragma unroll
    for (int i = 0; i < 4; i++) {
        float4 v;
        #pragma unroll
        for (int j = 0; j < 4; j++) {
            float2 f = unpk(acc2[i][j]);
            ((float*)&v)[j] = f.x + f.y;
        }
        *(float4*)&g_qkvg[(size_t)(m0 + ty * 4 + i) * FDIM + f0 + tx * 4] = v;
    }
}

// ---------------------------------------------------------------------------
// Kernel 2: attention per (b, h) block. 256 threads; thread t owns query row t.
// K/V streamed through smem in two 128-row halves (33 KB static smem).
// Smem reads in the hot loops are warp-broadcasts (all lanes same addr).
// Online softmax carries state across halves. f32x2 FMA throughout.
// ---------------------------------------------------------------------------
__global__ __launch_bounds__(256) void k_attn(const float* __restrict__ mask,
                                              const float* __restrict__ bias,
                                              const float* __restrict__ gbias) {
    __shared__ __align__(16) float Ks[128 * 32];   // 16 KB
    __shared__ __align__(16) float Vs[128 * 32];   // 16 KB
    __shared__ float maskS[256];                   // 1 KB

    const int tid = threadIdx.x;
    const int b = blockIdx.x;
    const int h = blockIdx.y;

    if (tid < 64) {
        *(float4*)&maskS[tid * 4] = *(const float4*)&mask[b * 256 + tid * 4];
    }

    // q row as 16 packed pairs (pre-scaled)
    const u64 scale2 = bcast2(0.17677669529663688f);  // 1/sqrt(32)
    u64 qd[16];
    {
        const u64* qp = (const u64*)(g_qkvg + (size_t)(b * 256 + tid) * FDIM + h * CH);
        #pragma unroll
        for (int c2 = 0; c2 < 16; c2++) {
            u64 v = qp[c2];
            fmul2(qd[c2], v, scale2);
        }
    }

    const float* biasRow = bias + (size_t)h * 65536 + (size_t)tid * 256;

    u64 accD[16] = {};
    float mcur = -1e30f, l = 0.f;

    #pragma unroll 1
    for (int half = 0; half < 2; half++) {
        __syncthreads();   // previous half fully consumed before overwrite
        // load K,V rows [half*128, half*128+128): 1024 float4 each, 4/thread
        #pragma unroll
        for (int i = 0; i < 4; i++) {
            int idx = tid + i * 256;
            int row = idx >> 3, c4 = idx & 7;
            const float* base =
                g_qkvg + (size_t)(b * 256 + half * 128 + row) * FDIM + h * CH + c4 * 4;
            *(float4*)&Ks[row * 32 + c4 * 4] = *(const float4*)(base + 128);
            *(float4*)&Vs[row * 32 + c4 * 4] = *(const float4*)(base + 256);
        }
        __syncthreads();

        for (int j0 = 0; j0 < 128; j0 += 32) {
            const int jg = half * 128 + j0;   // global key offset
            float s[32];
            // init with bias + mask term
            #pragma unroll
            for (int j4 = 0; j4 < 8; j4++) {
                float4 bv = *(const float4*)&biasRow[jg + j4 * 4];
                s[j4 * 4 + 0] = bv.x + (maskS[jg + j4 * 4 + 0] - 1.f) * INFV;
                s[j4 * 4 + 1] = bv.y + (maskS[jg + j4 * 4 + 1] - 1.f) * INFV;
                s[j4 * 4 + 2] = bv.z + (maskS[jg + j4 * 4 + 2] - 1.f) * INFV;
                s[j4 * 4 + 3] = bv.w + (maskS[jg + j4 * 4 + 3] - 1.f) * INFV;
            }
            // scores: paired dot, 2 accumulators for latency cover
            #pragma unroll
            for (int j = 0; j < 32; j++) {
                const u64* kr = (const u64*)&Ks[(j0 + j) * 32];
                u64 d2a = 0, d2b = 0;
                #pragma unroll
                for (int c2 = 0; c2 < 16; c2 += 2) {
                    ffma2(d2a, qd[c2], kr[c2]);
                    ffma2(d2b, qd[c2 + 1], kr[c2 + 1]);
                }
                float2 fa = unpk(d2a), fb = unpk(d2b);
                s[j] += (fa.x + fa.y) + (fb.x + fb.y);
            }
            // tile max
            float tm = s[0];
            #pragma unroll
            for (int j = 1; j < 32; j++) tm = fmaxf(tm, s[j]);
            float mnew = fmaxf(mcur, tm);
            float alpha = __expf(mcur - mnew);
            l *= alpha;
            u64 al2 = bcast2(alpha);
            #pragma unroll
            for (int c2 = 0; c2 < 16; c2++) fmul2(accD[c2], accD[c2], al2);
            // exp + AV (paired)
            #pragma unroll
            for (int j = 0; j < 32; j++) {
                float p = __expf(s[j] - mnew);
                l += p;
                u64 p2 = bcast2(p);
                const u64* vr = (const u64*)&Vs[(j0 + j) * 32];
                #pragma unroll
                for (int c2 = 0; c2 < 16; c2++) ffma2(accD[c2], p2, vr[c2]);
            }
            mcur = mnew;
        }
    }

    // epilogue: normalize + sigmoid gate, write g_og
    const float inv = 1.f / l;
    const size_t m = (size_t)b * 256 + tid;
    const float* grow = g_qkvg + m * FDIM + 384 + h * CH;
    float* orow = g_og + m * HC + h * CH;
    #pragma unroll
    for (int c4 = 0; c4 < 8; c4++) {
        float4 gv = *(const float4*)(grow + c4 * 4);
        float4 gb = *(const float4*)(gbias + h * CH + c4 * 4);
        float2 a0 = unpk(accD[c4 * 2]);
        float2 a1 = unpk(accD[c4 * 2 + 1]);
        float4 o;
        o.x = a0.x * inv * (1.f / (1.f + __expf(-(gv.x + gb.x))));
        o.y = a0.y * inv * (1.f / (1.f + __expf(-(gv.y + gb.y))));
        o.z = a1.x * inv * (1.f / (1.f + __expf(-(gv.z + gb.z))));
        o.w = a1.y * inv * (1.f / (1.f + __expf(-(gv.w + gb.w))));
        *(float4*)(orow + c4 * 4) = o;
    }
}

// ---------------------------------------------------------------------------
// Kernel 3: output projection + bias + transposed add + transposed store.
// Same swizzled-tile GEMM as K1.
// proj[m][oc] = dot(g_og[m], W_o[oc]) + b_o[oc]
// out[0,s,b,oc] = add[0,s,b,oc] + proj[0,b,s,oc]   (m = b*256 + s)
// ---------------------------------------------------------------------------
__global__ __launch_bounds__(256) void k_out(const float* __restrict__ Wo,
                                             const float* __restrict__ bo,
                                             const float* __restrict__ add,
                                             float* __restrict__ out) {
    __shared__ __align__(16) float As[64][64];
    __shared__ __align__(16) float Ws[64][64];
    const int tid = threadIdx.x;
    const int tx = tid & 15, ty = tid >> 4;
    const int m0 = blockIdx.x * 64;
    const int f0 = blockIdx.y * 64;

    u64 acc2[4][4] = {};

    #pragma unroll
    for (int kt = 0; kt < 2; kt++) {
        #pragma unroll
        for (int i = 0; i < 4; i++) {
            int idx = tid + i * 256;
            int row = idx >> 4, c4 = idx & 15;
            int sc4 = c4 ^ ((row >> 2) & 15);
            *(float4*)&As[row][sc4 * 4] =
                *(const float4*)&g_og[(size_t)(m0 + row) * HC + kt * 64 + c4 * 4];
            *(float4*)&Ws[row][sc4 * 4] =
                *(const float4*)&Wo[(size_t)(f0 + row) * HC + kt * 64 + c4 * 4];
        }
        __syncthreads();
        #pragma unroll
        for (int k4 = 0; k4 < 16; k4++) {
            const int pa = (k4 ^ ty) * 4;
            const int pb = (k4 ^ tx) * 4;
            ulonglong2 a2[4], b2[4];
            #pragma unroll
            for (int i = 0; i < 4; i++) a2[i] = *(const ulonglong2*)&As[ty * 4 + i][pa];
            #pragma unroll
            for (int j = 0; j < 4; j++) b2[j] = *(const ulonglong2*)&Ws[tx * 4 + j][pb];
            #pragma unroll
            for (int i = 0; i < 4; i++)
                #pragma unroll
                for (int j = 0; j < 4; j++) {
                    ffma2(acc2[i][j], a2[i].x, b2[j].x);
                    ffma2(acc2[i][j], a2[i].y, b2[j].y);
                }
        }
        __syncthreads();
    }

    const float4 bo4 = *(const float4*)&bo[f0 + tx * 4];
    #pragma unroll
    for (int i = 0; i < 4; i++) {
        int m = m0 + ty * 4 + i;
        int bb = m >> 8, ss = m & 255;
        size_t oidx = ((size_t)ss * 256 + bb) * 128 + f0 + tx * 4;
        float4 ad = *(const float4*)&add[oidx];
        float2 f0v = unpk(acc2[i][0]), f1v = unpk(acc2[i][1]);
        float2 f2v = unpk(acc2[i][2]), f3v = unpk(acc2[i][3]);
        float4 v;
        v.x = (f0v.x + f0v.y) + bo4.x + ad.x;
        v.y = (f1v.x + f1v.y) + bo4.y + ad.y;
        v.z = (f2v.x + f2v.y) + bo4.z + ad.z;
        v.w = (f3v.x + f3v.y) + bo4.w + ad.w;
        *(float4*)&out[oidx] = v;
    }
}

// ---------------------------------------------------------------------------
extern "C" void kernel_launch(void* const* d_in, const int* in_sizes, int n_in,
                              void* d_out, int out_size) {
    const float* x     = (const float*)d_in[0];  // input_qkv [1,256,256,128]
    const float* mask  = (const float*)d_in[1];  // [1,256,1,1,256]
    const float* bias  = (const float*)d_in[2];  // [1,1,4,256,256]
    const float* add   = (const float*)d_in[3];  // [1,256,256,128]
    const float* Wq    = (const float*)d_in[4];  // [512,128]
    const float* gb    = (const float*)d_in[5];  // [128]
    const float* Wo    = (const float*)d_in[6];  // [128,128]
    const float* bo    = (const float*)d_in[7];  // [128]
    float* out = (float*)d_out;

    k_qkvg<<<dim3(MTOT / 64, FDIM / 64), 256>>>(x, Wq);
    k_attn<<<dim3(BATCH, NH), 256>>>(mask, bias, gb);
    k_out<<<dim3(MTOT / 64, HC / 64), 256>>>(Wo, bo, add, out);
}